// round 13
// baseline (speedup 1.0000x reference)
#include <cuda_runtime.h>
#include <cuda_fp16.h>
#include <cstdint>

// ============================================================================
// BQQLinear collapsed to:  out = quant8(x) @ W + bias
//   quant8(x) = s * q,  q integer in [-127,127]  -> q exact in fp16
//   W (fp32) -> fp16 ;  out = s * ( q @ W_fp16 ) + bias
// SINGLE persistent kernel: 128 CTAs x 512 threads.
//   Phase A: quant x -> g_Aq        (each CTA a contiguous slice)
//   Phase B: build Wt fp16 -> g_Wt  (8 (j,k) pairs per CTA, 2 at a time)
//   ticket grid barrier (graph-replay-safe, all CTAs resident)
//   Phase C: mma.sync GEMM, CTA 128x128, 16 warps = 8 pos (64x32) x 2 kg.
// ============================================================================

#define PP 2
#define JJ 32
#define KK 32
#define MM 32
#define LL 8
#define NN 32

#define GEMM_M 2048
#define GEMM_N 1024
#define GEMM_K 1024

#define BM 128
#define BN 128
#define BKC 64
#define NCHUNK (GEMM_K / BKC)      // 16

#define SM_STRIDE 72               // fp16/row (64 + 8 pad) -> 144 B
#define A_TILE_BYTES (BM * SM_STRIDE * 2)             // 18432
#define B_TILE_BYTES (BN * SM_STRIDE * 2)             // 18432
#define STAGE_BYTES (A_TILE_BYTES + B_TILE_BYTES)     // 36864
#define NSTAGE 3
#define DSMEM_BYTES (NSTAGE * STAGE_BYTES + 256)      // 110848

#define NTHREADS 512               // 16 warps
#define NCTAS 128

// Device-global scratch (allocation-free rule)
__device__ __half g_Aq[GEMM_M * GEMM_K];   // 4 MB: fp16(q)
__device__ __half g_Wt[GEMM_N * GEMM_K];   // 2 MB: Wt fp16 (N-major, K contiguous)
__device__ unsigned int g_bar;             // ticket barrier counter (never reset)

// ---------------------------------------------------------------------------
// helpers
// ---------------------------------------------------------------------------
__device__ __forceinline__ uint32_t smem_u32(const void* p) {
    uint32_t a;
    asm("{ .reg .u64 t; cvta.to.shared.u64 t, %1; cvt.u32.u64 %0, t; }"
        : "=r"(a) : "l"(p));
    return a;
}

__device__ __forceinline__ void ldsm_x4(uint32_t* r, uint32_t addr) {
    asm volatile("ldmatrix.sync.aligned.m8n8.x4.shared.b16 {%0,%1,%2,%3}, [%4];"
                 : "=r"(r[0]), "=r"(r[1]), "=r"(r[2]), "=r"(r[3]) : "r"(addr));
}

__device__ __forceinline__ void mma16816(float* c, const uint32_t* a,
                                         const uint32_t* b) {
    asm volatile(
        "mma.sync.aligned.m16n8k16.row.col.f32.f16.f16.f32 "
        "{%0,%1,%2,%3}, {%4,%5,%6,%7}, {%8,%9}, {%0,%1,%2,%3};"
        : "+f"(c[0]), "+f"(c[1]), "+f"(c[2]), "+f"(c[3])
        : "r"(a[0]), "r"(a[1]), "r"(a[2]), "r"(a[3]), "r"(b[0]), "r"(b[1]));
}

#define CP_ASYNC16(dst, src) \
    asm volatile("cp.async.cg.shared.global [%0], [%1], 16;" \
                 :: "r"(dst), "l"(src) : "memory")
#define CP_COMMIT() asm volatile("cp.async.commit_group;" ::: "memory")
#define CP_WAIT(n)  asm volatile("cp.async.wait_group %0;" :: "n"(n) : "memory")

__device__ __forceinline__ float sgnf(float v) {
    return (v > 0.f) ? 1.f : ((v < 0.f) ? -1.f : 0.f);
}

// W-build per-half scratch (two halves of 256 threads work 2 pairs at once)
struct WBuildSmem {
    float sY[PP][MM * LL];     // 2 KB
    float sZ[PP][LL * NN];     // 2 KB
    float wpY[PP][8], wpZ[PP][8];
    float ysh[PP], zsh[PP];
    float aSh[PP][4];
    float Ysum[PP][MM];
    float Zsum[PP][NN];
};

extern __shared__ char dynsmem[];

// ----------------------------------------------------------------------------
// Fused persistent kernel
// ----------------------------------------------------------------------------
__global__ __launch_bounds__(NTHREADS, 1) void bqq_kernel(
    const float* __restrict__ x,
    const float* __restrict__ Y,   // (p,j,k,m,l)
    const float* __restrict__ Z,   // (p,j,k,l,n)
    const float* __restrict__ A,   // (p,j,k,4)
    const float* __restrict__ bias,
    const float* __restrict__ act_scale,
    float* __restrict__ out)
{
    const int tid  = threadIdx.x;
    const int cta  = blockIdx.y * gridDim.x + blockIdx.x;   // 0..127

    uint32_t raw = smem_u32(dynsmem);
    uint32_t sbase = (raw + 127u) & ~127u;

    const float sval = fmaxf(fabsf(act_scale[0]), 1e-8f);

    // ======================= Phase A: quant =======================
    {
        const float inv = 1.0f / sval;
        const float4* xv = (const float4*)x;
        __half2* o = (__half2*)g_Aq;
        int i = cta * 4096 + tid;          // 4096 float4 per CTA
        #pragma unroll
        for (int t = 0; t < 8; ++t, i += NTHREADS) {
            float4 v = xv[i];
            float q0 = fminf(fmaxf(rintf(v.x * inv), -127.f), 127.f);
            float q1 = fminf(fmaxf(rintf(v.y * inv), -127.f), 127.f);
            float q2 = fminf(fmaxf(rintf(v.z * inv), -127.f), 127.f);
            float q3 = fminf(fmaxf(rintf(v.w * inv), -127.f), 127.f);
            o[2 * i + 0] = __floats2half2_rn(q0, q1);
            o[2 * i + 1] = __floats2half2_rn(q2, q3);
        }
    }

    // ======================= Phase B: build Wt =======================
    {
        const int half = tid >> 8;      // 0 or 1
        const int htid = tid & 255;     // 0..255 within half
        const int lane = tid & 31;
        const int wrp  = htid >> 5;     // 0..7 within half

        WBuildSmem* ws = ((WBuildSmem*)(dynsmem + (sbase - raw))) + half;

        for (int it = 0; it < 4; ++it) {
            const int pair = cta * 8 + it * 2 + half;   // 0..1023
            const int j = pair >> 5;
            const int k = pair & 31;

            #pragma unroll
            for (int p = 0; p < PP; ++p) {
                size_t base = ((size_t)((p * JJ + j) * KK + k)) * 256;
                float y = Y[base + htid];
                float z = Z[base + htid];
                ws->sY[p][htid] = sgnf(y);
                ws->sZ[p][htid] = sgnf(z);
                float ay = fabsf(y), az = fabsf(z);
                #pragma unroll
                for (int off = 16; off > 0; off >>= 1) {
                    ay += __shfl_xor_sync(0xFFFFFFFFu, ay, off);
                    az += __shfl_xor_sync(0xFFFFFFFFu, az, off);
                }
                if (lane == 0) { ws->wpY[p][wrp] = ay; ws->wpZ[p][wrp] = az; }
            }
            __syncthreads();
            if (htid < PP) {
                float sy = 0.f, sz = 0.f;
                #pragma unroll
                for (int w = 0; w < 8; ++w) { sy += ws->wpY[htid][w]; sz += ws->wpZ[htid][w]; }
                ws->ysh[htid] = sy * (1.0f / 256.0f);
                ws->zsh[htid] = sz * (1.0f / 256.0f);
            }
            if (htid >= 32 && htid < 32 + PP * 4) {
                int t = htid - 32;
                int p = t >> 2, c = t & 3;
                ws->aSh[p][c] = A[((size_t)(p * JJ + j) * KK + k) * 4 + c];
            }
            if (htid >= 64 && htid < 128) {
                int t = htid - 64;
                int p = t >> 5, m = t & 31;
                float s = 0.f;
                #pragma unroll
                for (int l = 0; l < LL; ++l) s += ws->sY[p][m * LL + l];
                ws->Ysum[p][m] = s;
            } else if (htid >= 128 && htid < 192) {
                int t = htid - 128;
                int p = t >> 5, n = t & 31;
                float s = 0.f;
                #pragma unroll
                for (int l = 0; l < LL; ++l) s += ws->sZ[p][l * NN + n];
                ws->Zsum[p][n] = s;
            }
            __syncthreads();

            #pragma unroll
            for (int t = 0; t < 4; ++t) {
                int idx = t * 256 + htid;
                int m = idx >> 5;
                int n = idx & 31;
                float w = 0.f;
                #pragma unroll
                for (int p = 0; p < PP; ++p) {
                    float dot = 0.f;
                    #pragma unroll
                    for (int l = 0; l < LL; ++l)
                        dot += ws->sY[p][m * LL + l] * ws->sZ[p][l * NN + n];
                    float ys = ws->ysh[p], zs = ws->zsh[p];
                    w += ws->aSh[p][0] * ys * zs * dot
                       + ws->aSh[p][1] * ys * ws->Ysum[p][m]
                       + ws->aSh[p][2] * zs * ws->Zsum[p][n]
                       + ws->aSh[p][3];
                }
                size_t off = (size_t)(j * MM + m) * GEMM_K + (k * NN + n);
                g_Wt[off] = __float2half_rn(w);
            }
            __syncthreads();
        }
    }

    // ======================= grid barrier (ticket, replay-safe) ==============
    __syncthreads();
    if (tid == 0) {
        __threadfence();
        unsigned t = atomicAdd(&g_bar, 1u);
        unsigned target = (t - (t & (NCTAS - 1u))) + NCTAS;
        unsigned cur;
        do { cur = atomicAdd(&g_bar, 0u); } while ((int)(cur - target) < 0);
        __threadfence();
    }
    __syncthreads();

    // ======================= Phase C: GEMM =======================
    const int wid  = tid >> 5;
    const int lane = tid & 31;
    const int n0 = blockIdx.x * BN;
    const int m0 = blockIdx.y * BM;

    const int pos    = wid & 7;          // tile position
    const int warp_m = pos & 1;          // rows warp_m*64
    const int warp_n = pos >> 1;         // cols warp_n*32 (0..3)
    const int kg     = wid >> 3;         // k-group

    const __half* Aq = g_Aq + (size_t)m0 * GEMM_K;
    const __half* Wp = g_Wt + (size_t)n0 * GEMM_K;

    auto load_chunk = [&](int c, int buf) {
        const int k0 = c * BKC;
        uint32_t base = sbase + buf * STAGE_BYTES;
        #pragma unroll
        for (int it = 0; it < 4; ++it) {
            int s = it * NTHREADS + tid;  // 0..2047
            int row = s >> 3;             // 0..255
            int seg = s & 7;              // 0..7
            uint32_t dst = base + (uint32_t)(row * (SM_STRIDE * 2) + seg * 16);
            if (row < BM) {
                size_t goff = (size_t)row * GEMM_K + k0 + seg * 8;
                CP_ASYNC16(dst, Aq + goff);
            } else {
                size_t goff = (size_t)(row - BM) * GEMM_K + k0 + seg * 8;
                CP_ASYNC16(dst, Wp + goff);
            }
        }
    };

    float acc[4][4][4];
    #pragma unroll
    for (int mi = 0; mi < 4; ++mi)
        #pragma unroll
        for (int ni = 0; ni < 4; ++ni)
            #pragma unroll
            for (int q = 0; q < 4; ++q) acc[mi][ni][q] = 0.f;

    const int aRowT = warp_m * 64 + (lane & 15);
    const int aKT   = (lane >> 4) * 8;
    const int grp = lane >> 3, ln = lane & 7;
    const int bRowBase = BM + warp_n * 32 + (grp >> 1) * 8 + ln;
    const int bKT = (grp & 1) * 8;
    const int kgOff = kg * 32;

    load_chunk(0, 0); CP_COMMIT();
    load_chunk(1, 1); CP_COMMIT();

    for (int c = 0; c < NCHUNK; ++c) {
        const int buf = c % NSTAGE;
        if (c < NCHUNK - 1) { CP_WAIT(1); } else { CP_WAIT(0); }
        __syncthreads();

        if (c + 2 < NCHUNK) {
            load_chunk(c + 2, (c + 2) % NSTAGE);
            CP_COMMIT();
        }

        const uint32_t stg = sbase + buf * STAGE_BYTES;

        #pragma unroll
        for (int ksi = 0; ksi < 2; ++ksi) {
            const int ks = kgOff + ksi * 16;
            uint32_t afrag[4][4];
            #pragma unroll
            for (int mi = 0; mi < 4; ++mi) {
                uint32_t addr = stg +
                    (uint32_t)((aRowT + mi * 16) * (SM_STRIDE * 2) + (ks + aKT) * 2);
                ldsm_x4(afrag[mi], addr);
            }
            uint32_t bf[4][2];
            #pragma unroll
            for (int half = 0; half < 2; ++half) {
                uint32_t r[4];
                uint32_t addr = stg +
                    (uint32_t)((bRowBase + half * 16) * (SM_STRIDE * 2) + (ks + bKT) * 2);
                ldsm_x4(r, addr);
                bf[2 * half][0] = r[0]; bf[2 * half][1] = r[1];
                bf[2 * half + 1][0] = r[2]; bf[2 * half + 1][1] = r[3];
            }
            #pragma unroll
            for (int mi = 0; mi < 4; ++mi)
                #pragma unroll
                for (int ni = 0; ni < 4; ++ni)
                    mma16816(acc[mi][ni], afrag[mi], bf[ni]);
        }
    }

    // ---- split-K reduction ----
    __syncthreads();

    const uint32_t red_base = sbase + (uint32_t)pos * 8192;

    if (kg == 1) {
        #pragma unroll
        for (int mi = 0; mi < 4; ++mi)
            #pragma unroll
            for (int ni = 0; ni < 4; ++ni) {
                int jj = mi * 4 + ni;
                uint32_t addr = red_base + (uint32_t)((jj * 32 + lane) * 16);
                asm volatile("st.shared.v4.b32 [%0], {%1,%2,%3,%4};"
                             :: "r"(addr),
                                "r"(__float_as_uint(acc[mi][ni][0])),
                                "r"(__float_as_uint(acc[mi][ni][1])),
                                "r"(__float_as_uint(acc[mi][ni][2])),
                                "r"(__float_as_uint(acc[mi][ni][3])) : "memory");
            }
    }
    __syncthreads();

    if (kg == 0) {
        const int gID = lane >> 2;
        const int tig = lane & 3;

        #pragma unroll
        for (int mi = 0; mi < 4; ++mi) {
            const int rbase = m0 + warp_m * 64 + mi * 16 + gID;
            #pragma unroll
            for (int ni = 0; ni < 4; ++ni) {
                int jj = mi * 4 + ni;
                uint32_t addr = red_base + (uint32_t)((jj * 32 + lane) * 16);
                uint32_t r0, r1, r2, r3;
                asm volatile("ld.shared.v4.b32 {%0,%1,%2,%3}, [%4];"
                             : "=r"(r0), "=r"(r1), "=r"(r2), "=r"(r3) : "r"(addr));
                float a0 = acc[mi][ni][0] + __uint_as_float(r0);
                float a1 = acc[mi][ni][1] + __uint_as_float(r1);
                float a2 = acc[mi][ni][2] + __uint_as_float(r2);
                float a3 = acc[mi][ni][3] + __uint_as_float(r3);

                const int col = n0 + warp_n * 32 + ni * 8 + 2 * tig;
                const float b0 = bias[col], b1 = bias[col + 1];
                float2 v0, v1;
                v0.x = a0 * sval + b0;
                v0.y = a1 * sval + b1;
                v1.x = a2 * sval + b0;
                v1.y = a3 * sval + b1;
                *(float2*)(out + (size_t)rbase * GEMM_N + col) = v0;
                *(float2*)(out + (size_t)(rbase + 8) * GEMM_N + col) = v1;
            }
        }
    }
}

// ----------------------------------------------------------------------------
// Launch. Inputs (metadata order): x, Y_fp, Z_fp, A, bias, act_scale
// ----------------------------------------------------------------------------
extern "C" void kernel_launch(void* const* d_in, const int* in_sizes, int n_in,
                              void* d_out, int out_size) {
    const float* x         = (const float*)d_in[0];
    const float* Y_fp      = (const float*)d_in[1];
    const float* Z_fp      = (const float*)d_in[2];
    const float* A         = (const float*)d_in[3];
    const float* bias      = (const float*)d_in[4];
    const float* act_scale = (const float*)d_in[5];
    float* out = (float*)d_out;

    cudaFuncSetAttribute(bqq_kernel,
                         cudaFuncAttributeMaxDynamicSharedMemorySize, DSMEM_BYTES);

    dim3 gridG(GEMM_N / BN, GEMM_M / BM);   // 8 x 16 = 128 CTAs (all resident)
    bqq_kernel<<<gridG, NTHREADS, DSMEM_BYTES>>>(x, Y_fp, Z_fp, A, bias,
                                                 act_scale, out);
}

// round 14
// speedup vs baseline: 1.1582x; 1.1582x over previous
#include <cuda_runtime.h>
#include <cuda_fp16.h>
#include <cstdint>

// ============================================================================
// BQQLinear collapsed to:  out = quant8(x) @ W + bias
//   quant8(x) = s * q,  q integer in [-127,127]  -> q exact in fp16
//   W (fp32) -> fp16 ;  out = s * ( q @ W_fp16 ) + bias
// GEMM via mma.sync m16n8k16 f16 (fp32 accum), compute_103-safe PTX.
// CTA 128x128, 16 warps = 8 tile positions (64x32) x 2 K-groups; grid=128.
// Quant uses magic-number RNI rounding (FADD) instead of CVT-pipe rintf.
//   X: (M=2048, K=1024), Wt (N=1024, K=1024) K-major
// ============================================================================

#define PP 2
#define JJ 32
#define KK 32
#define MM 32
#define LL 8
#define NN 32

#define GEMM_M 2048
#define GEMM_N 1024
#define GEMM_K 1024

#define BM 128
#define BN 128
#define BKC 64
#define NCHUNK (GEMM_K / BKC)      // 16

#define SM_STRIDE 72               // fp16/row (64 + 8 pad) -> 144 B
#define A_TILE_BYTES (BM * SM_STRIDE * 2)             // 18432
#define B_TILE_BYTES (BN * SM_STRIDE * 2)             // 18432
#define STAGE_BYTES (A_TILE_BYTES + B_TILE_BYTES)     // 36864
#define NSTAGE 3
#define DSMEM_BYTES (NSTAGE * STAGE_BYTES + 256)      // 110848

#define NTHREADS 512               // 16 warps: 8 positions (64x32) x 2 kg

// Device-global scratch (allocation-free rule)
__device__ __half g_Aq[GEMM_M * GEMM_K];   // 4 MB: fp16(q)
__device__ __half g_Wt[GEMM_N * GEMM_K];   // 2 MB: Wt fp16 (N-major, K contiguous)

// ---------------------------------------------------------------------------
// helpers
// ---------------------------------------------------------------------------
__device__ __forceinline__ uint32_t smem_u32(const void* p) {
    uint32_t a;
    asm("{ .reg .u64 t; cvta.to.shared.u64 t, %1; cvt.u32.u64 %0, t; }"
        : "=r"(a) : "l"(p));
    return a;
}

__device__ __forceinline__ void ldsm_x4(uint32_t* r, uint32_t addr) {
    asm volatile("ldmatrix.sync.aligned.m8n8.x4.shared.b16 {%0,%1,%2,%3}, [%4];"
                 : "=r"(r[0]), "=r"(r[1]), "=r"(r[2]), "=r"(r[3]) : "r"(addr));
}

__device__ __forceinline__ void mma16816(float* c, const uint32_t* a,
                                         const uint32_t* b) {
    asm volatile(
        "mma.sync.aligned.m16n8k16.row.col.f32.f16.f16.f32 "
        "{%0,%1,%2,%3}, {%4,%5,%6,%7}, {%8,%9}, {%0,%1,%2,%3};"
        : "+f"(c[0]), "+f"(c[1]), "+f"(c[2]), "+f"(c[3])
        : "r"(a[0]), "r"(a[1]), "r"(a[2]), "r"(a[3]), "r"(b[0]), "r"(b[1]));
}

#define CP_ASYNC16(dst, src) \
    asm volatile("cp.async.cg.shared.global [%0], [%1], 16;" \
                 :: "r"(dst), "l"(src) : "memory")
#define CP_COMMIT() asm volatile("cp.async.commit_group;" ::: "memory")
#define CP_WAIT(n)  asm volatile("cp.async.wait_group %0;" :: "n"(n) : "memory")

__device__ __forceinline__ float sgnf(float v) {
    return (v > 0.f) ? 1.f : ((v < 0.f) ? -1.f : 0.f);
}

// round-to-nearest-even via magic constant (valid for |v| < 2^22; inputs are
// pre-clamped to [-127,127]).  __fadd_rn/__fsub_rn stop compiler reassociation.
#define RNI_MAGIC 12582912.0f   // 1.5 * 2^23
__device__ __forceinline__ float rni_fast(float v) {
    return __fsub_rn(__fadd_rn(v, RNI_MAGIC), RNI_MAGIC);
}
__device__ __forceinline__ float quant_q(float xval, float inv) {
    float v = fminf(fmaxf(xval * inv, -127.f), 127.f);   // clamp-then-round
    return rni_fast(v);                                   // == clip(round(x/s))
}

// ----------------------------------------------------------------------------
// Kernel 1 (fused prep):
//   blocks [0, 1024)    : build Wt (N-major fp16) for (j,k) pair
//   blocks [1024, 2048) : quantize x -> fp16 q (2 float4 per thread)
// ----------------------------------------------------------------------------
#define QBLOCKS 1024

__global__ __launch_bounds__(256) void prep_kernel(
    const float* __restrict__ x,
    const float* __restrict__ Y,   // (p,j,k,m,l)
    const float* __restrict__ Z,   // (p,j,k,l,n)
    const float* __restrict__ A,   // (p,j,k,4)
    const float* __restrict__ act_scale)
{
    const int tid = threadIdx.x;

    if (blockIdx.x >= 1024) {
        // ---- quant branch (FADD-based RNI; no CVT-pipe rintf) ----
        const float s = fmaxf(fabsf(act_scale[0]), 1e-8f);
        const float inv = 1.0f / s;
        const float4* xv = (const float4*)x;
        __half2* o = (__half2*)g_Aq;
        int i = (blockIdx.x - 1024) * 256 + tid;   // float4 index
        #pragma unroll
        for (int t = 0; t < 2; ++t, i += QBLOCKS * 256) {
            float4 v = xv[i];
            float q0 = quant_q(v.x, inv);
            float q1 = quant_q(v.y, inv);
            float q2 = quant_q(v.z, inv);
            float q3 = quant_q(v.w, inv);
            o[2 * i + 0] = __floats2half2_rn(q0, q1);
            o[2 * i + 1] = __floats2half2_rn(q2, q3);
        }
        return;
    }

    // ---- W-build branch ----
    const int j = blockIdx.x >> 5;
    const int k = blockIdx.x & 31;
    const int lane = tid & 31;
    const int wrp  = tid >> 5;

    __shared__ float sY[PP][MM * LL];
    __shared__ float sZ[PP][LL * NN];
    __shared__ float wpY[PP][8], wpZ[PP][8];
    __shared__ float ysh[PP], zsh[PP];
    __shared__ float aSh[PP][4];
    __shared__ float Ysum[PP][MM];
    __shared__ float Zsum[PP][NN];

    #pragma unroll
    for (int p = 0; p < PP; ++p) {
        size_t base = ((size_t)((p * JJ + j) * KK + k)) * 256;
        float y = Y[base + tid];
        float z = Z[base + tid];
        sY[p][tid] = sgnf(y);
        sZ[p][tid] = sgnf(z);
        float ay = fabsf(y), az = fabsf(z);
        #pragma unroll
        for (int off = 16; off > 0; off >>= 1) {
            ay += __shfl_xor_sync(0xFFFFFFFFu, ay, off);
            az += __shfl_xor_sync(0xFFFFFFFFu, az, off);
        }
        if (lane == 0) { wpY[p][wrp] = ay; wpZ[p][wrp] = az; }
    }
    __syncthreads();
    if (tid < PP) {
        float sy = 0.f, sz = 0.f;
        #pragma unroll
        for (int w = 0; w < 8; ++w) { sy += wpY[tid][w]; sz += wpZ[tid][w]; }
        ysh[tid] = sy * (1.0f / 256.0f);
        zsh[tid] = sz * (1.0f / 256.0f);
    }
    if (tid >= 32 && tid < 32 + PP * 4) {
        int t = tid - 32;
        int p = t >> 2, c = t & 3;
        aSh[p][c] = A[((size_t)(p * JJ + j) * KK + k) * 4 + c];
    }
    if (tid >= 64 && tid < 128) {
        int t = tid - 64;
        int p = t >> 5, m = t & 31;
        float s = 0.f;
        #pragma unroll
        for (int l = 0; l < LL; ++l) s += sY[p][m * LL + l];
        Ysum[p][m] = s;
    } else if (tid >= 128 && tid < 192) {
        int t = tid - 128;
        int p = t >> 5, n = t & 31;
        float s = 0.f;
        #pragma unroll
        for (int l = 0; l < LL; ++l) s += sZ[p][l * NN + n];
        Zsum[p][n] = s;
    }
    __syncthreads();

    #pragma unroll
    for (int t = 0; t < 4; ++t) {
        int idx = t * 256 + tid;
        int m = idx >> 5;
        int n = idx & 31;
        float w = 0.f;
        #pragma unroll
        for (int p = 0; p < PP; ++p) {
            float dot = 0.f;
            #pragma unroll
            for (int l = 0; l < LL; ++l)
                dot += sY[p][m * LL + l] * sZ[p][l * NN + n];
            float ys = ysh[p], zs = zsh[p];
            w += aSh[p][0] * ys * zs * dot
               + aSh[p][1] * ys * Ysum[p][m]
               + aSh[p][2] * zs * Zsum[p][n]
               + aSh[p][3];
        }
        size_t off = (size_t)(j * MM + m) * GEMM_K + (k * NN + n);
        g_Wt[off] = __float2half_rn(w);
    }
}

// ----------------------------------------------------------------------------
// Kernel 2: mma.sync GEMM  out = s * (q @ Wt^T) + bias
// CTA 128x128, 16 warps: 8 positions (64x32) x 2 K-groups, BK=64, 3 stages.
// ----------------------------------------------------------------------------
extern __shared__ char dynsmem[];

__global__ __launch_bounds__(NTHREADS, 1) void gemm_mma_kernel(
    const float* __restrict__ bias,
    const float* __restrict__ act_scale,
    float* __restrict__ out)
{
    const int tid  = threadIdx.x;
    const int wid  = tid >> 5;
    const int lane = tid & 31;
    const int n0 = blockIdx.x * BN;
    const int m0 = blockIdx.y * BM;

    const int pos    = wid & 7;          // 0..7 tile position
    const int warp_m = pos & 1;          // rows warp_m*64
    const int warp_n = pos >> 1;         // cols warp_n*32 (0..3)
    const int kg     = wid >> 3;         // k-group: k in [kg*32, kg*32+32)

    uint32_t raw = smem_u32(dynsmem);
    uint32_t sbase = (raw + 127u) & ~127u;

    const __half* Aq = g_Aq + (size_t)m0 * GEMM_K;
    const __half* Wp = g_Wt + (size_t)n0 * GEMM_K;

    auto load_chunk = [&](int c, int buf) {
        const int k0 = c * BKC;
        uint32_t base = sbase + buf * STAGE_BYTES;
        #pragma unroll
        for (int it = 0; it < 4; ++it) {
            int s = it * NTHREADS + tid;  // 0..2047
            int row = s >> 3;             // 0..255
            int seg = s & 7;              // 0..7
            uint32_t dst = base + (uint32_t)(row * (SM_STRIDE * 2) + seg * 16);
            if (row < BM) {
                size_t goff = (size_t)row * GEMM_K + k0 + seg * 8;
                CP_ASYNC16(dst, Aq + goff);
            } else {
                size_t goff = (size_t)(row - BM) * GEMM_K + k0 + seg * 8;
                CP_ASYNC16(dst, Wp + goff);
            }
        }
    };

    float acc[4][4][4];
    #pragma unroll
    for (int mi = 0; mi < 4; ++mi)
        #pragma unroll
        for (int ni = 0; ni < 4; ++ni)
            #pragma unroll
            for (int q = 0; q < 4; ++q) acc[mi][ni][q] = 0.f;

    const int aRowT = warp_m * 64 + (lane & 15);
    const int aKT   = (lane >> 4) * 8;
    const int grp = lane >> 3, ln = lane & 7;
    const int bRowBase = BM + warp_n * 32 + (grp >> 1) * 8 + ln;
    const int bKT = (grp & 1) * 8;
    const int kgOff = kg * 32;

    load_chunk(0, 0); CP_COMMIT();
    load_chunk(1, 1); CP_COMMIT();

    for (int c = 0; c < NCHUNK; ++c) {
        const int buf = c % NSTAGE;
        if (c < NCHUNK - 1) { CP_WAIT(1); } else { CP_WAIT(0); }
        __syncthreads();

        if (c + 2 < NCHUNK) {
            load_chunk(c + 2, (c + 2) % NSTAGE);
            CP_COMMIT();
        }

        const uint32_t stg = sbase + buf * STAGE_BYTES;

        #pragma unroll
        for (int ksi = 0; ksi < 2; ++ksi) {
            const int ks = kgOff + ksi * 16;
            uint32_t afrag[4][4];
            #pragma unroll
            for (int mi = 0; mi < 4; ++mi) {
                uint32_t addr = stg +
                    (uint32_t)((aRowT + mi * 16) * (SM_STRIDE * 2) + (ks + aKT) * 2);
                ldsm_x4(afrag[mi], addr);
            }
            uint32_t bf[4][2];
            #pragma unroll
            for (int half = 0; half < 2; ++half) {
                uint32_t r[4];
                uint32_t addr = stg +
                    (uint32_t)((bRowBase + half * 16) * (SM_STRIDE * 2) + (ks + bKT) * 2);
                ldsm_x4(r, addr);
                bf[2 * half][0] = r[0]; bf[2 * half][1] = r[1];
                bf[2 * half + 1][0] = r[2]; bf[2 * half + 1][1] = r[3];
            }
            #pragma unroll
            for (int mi = 0; mi < 4; ++mi)
                #pragma unroll
                for (int ni = 0; ni < 4; ++ni)
                    mma16816(acc[mi][ni], afrag[mi], bf[ni]);
        }
    }

    // ---- split-K reduction: kg=1 warps -> smem, kg=0 warps add ----
    __syncthreads();

    const uint32_t red_base = sbase + (uint32_t)pos * 8192;

    if (kg == 1) {
        #pragma unroll
        for (int mi = 0; mi < 4; ++mi)
            #pragma unroll
            for (int ni = 0; ni < 4; ++ni) {
                int jj = mi * 4 + ni;
                uint32_t addr = red_base + (uint32_t)((jj * 32 + lane) * 16);
                asm volatile("st.shared.v4.b32 [%0], {%1,%2,%3,%4};"
                             :: "r"(addr),
                                "r"(__float_as_uint(acc[mi][ni][0])),
                                "r"(__float_as_uint(acc[mi][ni][1])),
                                "r"(__float_as_uint(acc[mi][ni][2])),
                                "r"(__float_as_uint(acc[mi][ni][3])) : "memory");
            }
    }
    __syncthreads();

    if (kg == 0) {
        const float sval = fmaxf(fabsf(act_scale[0]), 1e-8f);
        const int gID = lane >> 2;
        const int tig = lane & 3;

        #pragma unroll
        for (int mi = 0; mi < 4; ++mi) {
            const int rbase = m0 + warp_m * 64 + mi * 16 + gID;
            #pragma unroll
            for (int ni = 0; ni < 4; ++ni) {
                int jj = mi * 4 + ni;
                uint32_t addr = red_base + (uint32_t)((jj * 32 + lane) * 16);
                uint32_t r0, r1, r2, r3;
                asm volatile("ld.shared.v4.b32 {%0,%1,%2,%3}, [%4];"
                             : "=r"(r0), "=r"(r1), "=r"(r2), "=r"(r3) : "r"(addr));
                float a0 = acc[mi][ni][0] + __uint_as_float(r0);
                float a1 = acc[mi][ni][1] + __uint_as_float(r1);
                float a2 = acc[mi][ni][2] + __uint_as_float(r2);
                float a3 = acc[mi][ni][3] + __uint_as_float(r3);

                const int col = n0 + warp_n * 32 + ni * 8 + 2 * tig;
                const float b0 = bias[col], b1 = bias[col + 1];
                float2 v0, v1;
                v0.x = a0 * sval + b0;
                v0.y = a1 * sval + b1;
                v1.x = a2 * sval + b0;
                v1.y = a3 * sval + b1;
                *(float2*)(out + (size_t)rbase * GEMM_N + col) = v0;
                *(float2*)(out + (size_t)(rbase + 8) * GEMM_N + col) = v1;
            }
        }
    }
}

// ----------------------------------------------------------------------------
// Launch. Inputs (metadata order): x, Y_fp, Z_fp, A, bias, act_scale
// ----------------------------------------------------------------------------
extern "C" void kernel_launch(void* const* d_in, const int* in_sizes, int n_in,
                              void* d_out, int out_size) {
    const float* x         = (const float*)d_in[0];
    const float* Y_fp      = (const float*)d_in[1];
    const float* Z_fp      = (const float*)d_in[2];
    const float* A         = (const float*)d_in[3];
    const float* bias      = (const float*)d_in[4];
    const float* act_scale = (const float*)d_in[5];
    float* out = (float*)d_out;

    cudaFuncSetAttribute(gemm_mma_kernel,
                         cudaFuncAttributeMaxDynamicSharedMemorySize, DSMEM_BYTES);

    // fused prep: W-build (1024 blocks) + quant (1024 blocks)
    prep_kernel<<<1024 + QBLOCKS, 256>>>(x, Y_fp, Z_fp, A, act_scale);

    dim3 gridG(GEMM_N / BN, GEMM_M / BM);   // 8 x 16 = 128 CTAs
    gemm_mma_kernel<<<gridG, NTHREADS, DSMEM_BYTES>>>(bias, act_scale, out);
}